// round 6
// baseline (speedup 1.0000x reference)
#include <cuda_runtime.h>
#include <math.h>

#define BSZ   4096
#define TSZ   1024
#define DIN   2
#define EMD   128
#define CELL  128
#define DOUT  5
#define GATES 512   /* 4*CELL */
#define KTOT  256   /* EMD + CELL */
#define NCTA  128
#define ROWS  32    /* batch rows per CTA */
#define NTHR  512
#define A2ST  36    /* A2 row stride (floats): even (8B pair align), 36%4==0 (16B align), 36%32==4 */
#define HSST  132   /* Hs row stride */
#define WOST  132

typedef unsigned long long ull;

/* ---------------- persistent device scratch ---------------- */
__device__ float g_Wcat[KTOT * GATES];   /* [k][n]: k<128 -> W_ih[n][k], else W_hh[n][k-128] */
__device__ float g_bias[GATES];          /* b_ih + b_hh */

/* ---------------- helpers ---------------- */
__device__ __forceinline__ ull pack2(float lo, float hi) {
    ull r; asm("mov.b64 %0, {%1, %2};" : "=l"(r) : "f"(lo), "f"(hi)); return r;
}
__device__ __forceinline__ void unpack2(ull v, float &lo, float &hi) {
    asm("mov.b64 {%0, %1}, %2;" : "=f"(lo), "=f"(hi) : "l"(v));
}
__device__ __forceinline__ void ffma2(ull &d, ull a, ull b) {
    asm("fma.rn.f32x2 %0, %1, %2, %0;" : "+l"(d) : "l"(a), "l"(b));
}
__device__ __forceinline__ float sigm(float x) {
    return __fdividef(1.0f, 1.0f + __expf(-x));
}
__device__ __forceinline__ float tanh_f(float x) {
    float e = __expf(-2.0f * fabsf(x));
    float r = __fdividef(1.0f - e, 1.0f + e);
    return copysignf(r, x);
}
__device__ __forceinline__ void cp16(void* s, const void* g) {
    unsigned sa = (unsigned)__cvta_generic_to_shared(s);
    asm volatile("cp.async.cg.shared.global [%0], [%1], 16;" :: "r"(sa), "l"(g));
}
__device__ __forceinline__ void cp_commit() { asm volatile("cp.async.commit_group;"); }
__device__ __forceinline__ void cp_wait0()  { asm volatile("cp.async.wait_group 0;" ::: "memory"); }

/* stage one 8-k weight chunk (16KB): 1024 float4 over 512 threads */
__device__ __forceinline__ void prefetch_chunk(float* Bbuf, int c, int tid) {
    const float4* src = (const float4*)(g_Wcat + c * 8 * GATES);
    float4* dst = (float4*)Bbuf;
    cp16(dst + tid,        src + tid);
    cp16(dst + tid + NTHR, src + tid + NTHR);
    cp_commit();
}

/* ---------------- setup ---------------- */
__global__ void setup_kernel(const float* __restrict__ W_ih, const float* __restrict__ W_hh,
                             const float* __restrict__ b_ih, const float* __restrict__ b_hh) {
    int idx = blockIdx.x * blockDim.x + threadIdx.x;
    if (idx < KTOT * GATES) {
        int k = idx / GATES, n = idx % GATES;
        g_Wcat[idx] = (k < EMD) ? W_ih[n * EMD + k] : W_hh[n * CELL + (k - EMD)];
    }
    if (idx < GATES) g_bias[idx] = b_ih[idx] + b_hh[idx];
}

/* ---------------- persistent kernel ----------------
 * 128 CTAs x 512 threads (16 warps -> 4/SMSP). CTA owns 32 batch rows.
 * Thread tile: 1 cell x 8 rows (4 row-pairs packed in f32x2) x 4 gates -> 16 f32x2 accs.
 * A2 layout: [k][row] (k-major, row-contiguous) -> LDS.128 broadcast yields 2 row-pairs, no packing MOVs.
 * B read: coalesced scalar LDS.32 per gate, duplicated into a pair.
 * smem (floats):
 *   A2  [0,      9216)  [256][36]
 *   Bs0 [9216,  13312)
 *   Bs1 [13312, 17408)
 *   Hs  [17408, 21632)  h row-major [32][132] for y-phase/tail
 *   WoS [21632, 22292)
 *   WeS [22292, 22548)
 *   beS [22548, 22676)
 *   biaS[22676, 23188)
 *   xs  [23188, 23252)
 */
#define SMEM_FLOATS 23252

__global__ void __launch_bounds__(NTHR, 1)
lstm_persist(const float* __restrict__ inputs,
             const float* __restrict__ We,  const float* __restrict__ be,
             const float* __restrict__ Wo,  const float* __restrict__ bov,
             float* __restrict__ out) {
    extern __shared__ float smf[];
    float*  A2   = smf;
    float*  Bs0  = smf + 9216;
    float*  Bs1  = smf + 13312;
    float*  Hs   = smf + 17408;
    float*  WoS  = smf + 21632;
    float*  WeS  = smf + 22292;
    float*  beS  = smf + 22548;
    float*  biaS = smf + 22676;
    float2* xs   = (float2*)(smf + 23188);

    const int tid  = threadIdx.x;
    const int row0 = blockIdx.x * ROWS;
    const int cell = tid & 127;    /* this thread's cell */
    const int rg   = tid >> 7;     /* row group: rows 8*rg .. 8*rg+7 */

    /* preload small weights */
    for (int i = tid; i < DOUT * CELL; i += NTHR) WoS[(i / CELL) * WOST + (i % CELL)] = Wo[i];
    for (int i = tid; i < EMD; i += NTHR) {
        WeS[2 * i] = We[2 * i]; WeS[2 * i + 1] = We[2 * i + 1]; beS[i] = be[i];
    }
    for (int i = tid; i < GATES; i += NTHR) biaS[i] = g_bias[i];
    /* zero h-region of A2 */
    for (int i = tid; i < CELL * ROWS; i += NTHR)
        A2[(EMD + (i >> 5)) * A2ST + (i & 31)] = 0.0f;
    __syncthreads();

    /* per-thread packed gate biases (acc reset values) */
    ull bb[4];
#pragma unroll
    for (int g = 0; g < 4; g++) { float b = biaS[g * 128 + cell]; bb[g] = pack2(b, b); }

    float cst[8];                       /* c state: 8 rows x this cell */
#pragma unroll
    for (int i = 0; i < 8; i++) cst[i] = 0.0f;

    ull acc[4][4];                      /* [row-pair][gate] */
#pragma unroll
    for (int rp = 0; rp < 4; rp++)
#pragma unroll
        for (int g = 0; g < 4; g++) acc[rp][g] = bb[g];

    const float bo_r = (tid < ROWS * DOUT) ? bov[tid % DOUT] : 0.0f;
    const int ej = tid >> 2;            /* e-phase: this thread's j */
    const int er0 = (tid & 3) * 8;      /* e-phase: first row */

    prefetch_chunk(Bs0, 0, tid);

    for (int t = 0; t < TSZ; t++) {
        /* ---- e-phase (A2 e-region for step t) + stage x for THIS step first ---- */
        if (tid < ROWS)
            xs[tid] = ((const float2*)inputs)[(size_t)(row0 + tid) * TSZ + t];
        __syncthreads();                          /* xs ready; prev y-phase done */

        {
            float w0 = WeS[2 * ej], w1 = WeS[2 * ej + 1], bj = beS[ej];
#pragma unroll
            for (int i = 0; i < 8; i++) {
                int r = er0 + i;
                float2 x = xs[r];
                A2[ej * A2ST + r] = fmaxf(fmaf(w0, x.x, fmaf(w1, x.y, bj)), 0.0f);
            }
        }

        /* ---- GEMM: gates[32,512] += A[32,256] @ Wcat[256,512] ---- */
        for (int c = 0; c < 32; c++) {
            cp_wait0();
            __syncthreads();              /* chunk c arrived; A2 complete (c==0) */
            bool lastall = (t == TSZ - 1) && (c == 31);
            if (!lastall) {
                int nc = (c < 31) ? c + 1 : 0;
                prefetch_chunk((nc & 1) ? Bs1 : Bs0, nc, tid);
            }
            const float* Bc = (c & 1) ? Bs1 : Bs0;
#pragma unroll
            for (int kk = 0; kk < 8; kk++) {
                const int k = c * 8 + kk;
                /* A: two LDS.128 broadcasts -> 4 row-pairs, already packed */
                ulonglong2 aLo = *(const ulonglong2*)&A2[k * A2ST + rg * 8];
                ulonglong2 aHi = *(const ulonglong2*)&A2[k * A2ST + rg * 8 + 4];
                /* B: coalesced scalars, duplicate into pairs */
                const float* brow = Bc + kk * GATES + cell;
                ull b0 = pack2(brow[0],   brow[0]);
                ull b1 = pack2(brow[128], brow[128]);
                ull b2 = pack2(brow[256], brow[256]);
                ull b3 = pack2(brow[384], brow[384]);
                ffma2(acc[0][0], aLo.x, b0); ffma2(acc[0][1], aLo.x, b1);
                ffma2(acc[0][2], aLo.x, b2); ffma2(acc[0][3], aLo.x, b3);
                ffma2(acc[1][0], aLo.y, b0); ffma2(acc[1][1], aLo.y, b1);
                ffma2(acc[1][2], aLo.y, b2); ffma2(acc[1][3], aLo.y, b3);
                ffma2(acc[2][0], aHi.x, b0); ffma2(acc[2][1], aHi.x, b1);
                ffma2(acc[2][2], aHi.x, b2); ffma2(acc[2][3], aHi.x, b3);
                ffma2(acc[3][0], aHi.y, b0); ffma2(acc[3][1], aHi.y, b1);
                ffma2(acc[3][2], aHi.y, b2); ffma2(acc[3][3], aHi.y, b3);
            }
        }
        __syncthreads();                 /* GEMM done reading A2 h-region */

        /* ---- LSTM pointwise: rows 8rg..8rg+7, this cell ---- */
#pragma unroll
        for (int rp = 0; rp < 4; rp++) {
            float gia, gib, gfa, gfb, gga, ggb, goa, gob;
            unpack2(acc[rp][0], gia, gib);
            unpack2(acc[rp][1], gfa, gfb);
            unpack2(acc[rp][2], gga, ggb);
            unpack2(acc[rp][3], goa, gob);
            int ra = rg * 8 + 2 * rp;
            {
                float iv = sigm(gia), fv = sigm(gfa), gv = tanh_f(gga), ov = sigm(goa);
                cst[2 * rp] = fmaf(fv, cst[2 * rp], iv * gv);
                float hn = ov * tanh_f(cst[2 * rp]);
                Hs[ra * HSST + cell] = hn;
                A2[(EMD + cell) * A2ST + ra] = hn;
            }
            {
                float iv = sigm(gib), fv = sigm(gfb), gv = tanh_f(ggb), ov = sigm(gob);
                cst[2 * rp + 1] = fmaf(fv, cst[2 * rp + 1], iv * gv);
                float hn = ov * tanh_f(cst[2 * rp + 1]);
                Hs[(ra + 1) * HSST + cell] = hn;
                A2[(EMD + cell) * A2ST + ra + 1] = hn;
            }
            acc[rp][0] = bb[0]; acc[rp][1] = bb[1];
            acc[rp][2] = bb[2]; acc[rp][3] = bb[3];
        }
        __syncthreads();                 /* h_new visible */

        /* ---- output MLP: y[32,5] = h_new @ Wo^T + bo ---- */
        if (tid < ROWS * DOUT) {
            int r = tid / DOUT, d = tid % DOUT;
            float s = bo_r;
            const float* hrow = Hs + r * HSST;
            const float* wrow = WoS + d * WOST;
#pragma unroll 16
            for (int j = 0; j < CELL; j++) s = fmaf(hrow[j], wrow[j], s);
            out[((size_t)(row0 + r) * TSZ + t) * DOUT + d] = s;
        }
        /* next iteration's first sync orders y-phase before A2/xs overwrite */
    }

    /* ---- tail: final h (from Hs) and c (from regs) ---- */
    size_t baseH = (size_t)BSZ * TSZ * DOUT;
    size_t baseC = baseH + (size_t)BSZ * CELL;
#pragma unroll
    for (int i = 0; i < 8; i++) {
        int idx = tid + i * NTHR;                 /* h: coalesced via Hs */
        int r = idx >> 7, cc = idx & 127;
        out[baseH + (size_t)(row0 + r) * CELL + cc] = Hs[r * HSST + cc];
    }
#pragma unroll
    for (int i = 0; i < 8; i++) {                 /* c: lanes differ in cell -> coalesced */
        int r = rg * 8 + i;
        out[baseC + (size_t)(row0 + r) * CELL + cell] = cst[i];
    }
}

/* ---------------- launch: 2 graph nodes ---------------- */
extern "C" void kernel_launch(void* const* d_in, const int* in_sizes, int n_in,
                              void* d_out, int out_size) {
    const float* inputs = (const float*)d_in[0];
    const float* We     = (const float*)d_in[1];
    const float* be     = (const float*)d_in[2];
    const float* W_ih   = (const float*)d_in[3];
    const float* W_hh   = (const float*)d_in[4];
    const float* b_ih   = (const float*)d_in[5];
    const float* b_hh   = (const float*)d_in[6];
    const float* Wo     = (const float*)d_in[7];
    const float* bo     = (const float*)d_in[8];
    float* out = (float*)d_out;

    static int smem_set = 0;
    if (!smem_set) {
        cudaFuncSetAttribute(lstm_persist, cudaFuncAttributeMaxDynamicSharedMemorySize,
                             SMEM_FLOATS * (int)sizeof(float));
        smem_set = 1;
    }

    setup_kernel<<<(KTOT * GATES + 255) / 256, 256>>>(W_ih, W_hh, b_ih, b_hh);
    lstm_persist<<<NCTA, NTHR, SMEM_FLOATS * sizeof(float)>>>(inputs, We, be, Wo, bo, out);
}

// round 7
// speedup vs baseline: 3.1382x; 3.1382x over previous
#include <cuda_runtime.h>
#include <cuda_bf16.h>
#include <math.h>

#define BSZ   4096
#define TSZ   1024
#define DIN   2
#define EMD   128
#define CELL  128
#define DOUT  5
#define GATES 512
#define KTOT  256
#define NCTA  128
#define ROWS  32
#define NTHR  512
#define APST  264            /* A plane row stride, bf16 elems (conflict-free: bank=4r+kp) */
#define HSST  132
#define WOST  132
#define NBF   (16*16*4*2*32*4)   /* 262144 bf16 = 512KB B-fragment array */

typedef unsigned int u32;

/* ---------------- persistent device scratch ---------------- */
__device__ __nv_bfloat16 g_B[NBF];   /* [kt][w][nt][plane][lane][4] pre-laid mma B frags */
__device__ float g_bias[GATES];      /* b_ih + b_hh, permuted-consistent (index = nt*128+cell) */

/* ---------------- helpers ---------------- */
__device__ __forceinline__ float sigm(float x) {
    return __fdividef(1.0f, 1.0f + __expf(-x));
}
__device__ __forceinline__ float tanh_f(float x) {
    float e = __expf(-2.0f * fabsf(x));
    float r = __fdividef(1.0f - e, 1.0f + e);
    return copysignf(r, x);
}
__device__ __forceinline__ void mma16816(float* d, const u32* a, u32 b0, u32 b1) {
    asm("mma.sync.aligned.m16n8k16.row.col.f32.bf16.bf16.f32 "
        "{%0,%1,%2,%3}, {%4,%5,%6,%7}, {%8,%9}, {%0,%1,%2,%3};"
        : "+f"(d[0]), "+f"(d[1]), "+f"(d[2]), "+f"(d[3])
        : "r"(a[0]), "r"(a[1]), "r"(a[2]), "r"(a[3]), "r"(b0), "r"(b1));
}

/* ---------------- setup: split weights to bf16 hi/lo mma fragments ----------------
 * Column permutation: mma n-column (w, nt, nl) -> gate nt, cell 8w+nl.
 * Fragment element j of lane l: k_local = 2*(l%4) + (j&1) + 8*(j>>1), n_local = l/4. */
__global__ void setup_kernel(const float* __restrict__ W_ih, const float* __restrict__ W_hh,
                             const float* __restrict__ b_ih, const float* __restrict__ b_hh) {
    int idx = blockIdx.x * blockDim.x + threadIdx.x;
    if (idx < NBF) {
        int j  = idx & 3;
        int l  = (idx >> 2) & 31;
        int p  = (idx >> 7) & 1;
        int nt = (idx >> 8) & 3;
        int w  = (idx >> 10) & 15;
        int kt = idx >> 14;
        int k  = kt * 16 + 2 * (l & 3) + (j & 1) + 8 * (j >> 1);
        int n  = nt * 128 + 8 * w + (l >> 2);
        float v = (k < EMD) ? W_ih[n * EMD + k] : W_hh[n * CELL + (k - EMD)];
        __nv_bfloat16 hi = __float2bfloat16_rn(v);
        g_B[idx] = p ? __float2bfloat16_rn(v - __bfloat162float(hi)) : hi;
    }
    if (idx < GATES) g_bias[idx] = b_ih[idx] + b_hh[idx];
}

/* ---------------- persistent kernel ----------------
 * 128 CTAs x 512 threads (16 warps). Warp w: all 32 rows x cells [8w, 8w+8) x all 4 gates.
 * GEMM: 3-term bf16 split mma (Ahi*Bhi + Ahi*Blo + Alo*Bhi), fp32 accum = fp32 precision.
 * A (e|h) in smem as bf16 hi/lo planes [32][264]; B frags streamed from L2 by LDG.
 * Accumulator layout puts i,f,g,o of each (row,cell) in ONE thread -> pointwise in regs.
 * smem (bytes):
 *   Ahi [0,     16896)   Alo [16896, 33792)   Hs [33792, 50688)
 *   WoS [50688, 53328)   WeS [53328, 54352)   beS[54352, 54864)   xs [54864, 55120) */
#define SMEM_BYTES 55120

__global__ void __launch_bounds__(NTHR, 1)
lstm_persist(const float* __restrict__ inputs,
             const float* __restrict__ We,  const float* __restrict__ be,
             const float* __restrict__ Wo,  const float* __restrict__ bov,
             float* __restrict__ out) {
    extern __shared__ char smc[];
    __nv_bfloat16* Ahi = (__nv_bfloat16*)smc;
    __nv_bfloat16* Alo = (__nv_bfloat16*)(smc + 16896);
    float*  Hs  = (float*)(smc + 33792);
    float*  WoS = (float*)(smc + 50688);
    float*  WeS = (float*)(smc + 53328);
    float*  beS = (float*)(smc + 54352);
    float2* xs  = (float2*)(smc + 54864);

    const int tid  = threadIdx.x;
    const int row0 = blockIdx.x * ROWS;
    const int w    = tid >> 5;
    const int l    = tid & 31;
    const int r0   = l >> 2;          /* frag row base */
    const int cp   = l & 3;           /* frag col-pair */
    const int cell0 = 8 * w + 2 * cp; /* this thread's first cell */

    /* preload small weights */
    for (int i = tid; i < DOUT * CELL; i += NTHR) WoS[(i / CELL) * WOST + (i % CELL)] = Wo[i];
    for (int i = tid; i < EMD; i += NTHR) {
        WeS[2 * i] = We[2 * i]; WeS[2 * i + 1] = We[2 * i + 1]; beS[i] = be[i];
    }
    /* zero h-region of A planes (h0 = 0) */
    for (int i = tid; i < ROWS * CELL; i += NTHR) {
        int r = i >> 7, c = i & 127;
        Ahi[r * APST + EMD + c] = __float2bfloat16_rn(0.0f);
        Alo[r * APST + EMD + c] = __float2bfloat16_rn(0.0f);
    }

    /* per-thread gate biases (accumulator init) */
    float bia[4][2];
#pragma unroll
    for (int nt = 0; nt < 4; nt++) {
        bia[nt][0] = g_bias[nt * 128 + cell0];
        bia[nt][1] = g_bias[nt * 128 + cell0 + 1];
    }

    float D[2][4][4];
#pragma unroll
    for (int mt = 0; mt < 2; mt++)
#pragma unroll
        for (int nt = 0; nt < 4; nt++) {
            D[mt][nt][0] = bia[nt][0]; D[mt][nt][1] = bia[nt][1];
            D[mt][nt][2] = bia[nt][0]; D[mt][nt][3] = bia[nt][1];
        }

    float cst[8];   /* c-state: [mt*4 + half*2 + cc] */
#pragma unroll
    for (int i = 0; i < 8; i++) cst[i] = 0.0f;

    const float bo_r = (tid < ROWS * DOUT) ? bov[tid % DOUT] : 0.0f;
    const int ej  = tid >> 2;
    const int er0 = (tid & 3) * 8;

    const __nv_bfloat16* gBw = g_B + w * 1024 + l * 4;

    for (int t = 0; t < TSZ; t++) {
        if (tid < ROWS)
            xs[tid] = ((const float2*)inputs)[(size_t)(row0 + tid) * TSZ + t];
        __syncthreads();   /* S1: xs ready; prev GEMM/y done */

        /* ---- e-phase: e = relu(We x + be), split to bf16 hi/lo planes ---- */
        {
            float w0 = WeS[2 * ej], w1 = WeS[2 * ej + 1], bj = beS[ej];
#pragma unroll
            for (int i = 0; i < 8; i++) {
                int r = er0 + i;
                float2 x = xs[r];
                float e = fmaxf(fmaf(w0, x.x, fmaf(w1, x.y, bj)), 0.0f);
                __nv_bfloat16 hi = __float2bfloat16_rn(e);
                Ahi[r * APST + ej] = hi;
                Alo[r * APST + ej] = __float2bfloat16_rn(e - __bfloat162float(hi));
            }
        }
        __syncthreads();   /* S2: A planes complete */

        /* ---- GEMM: 16 k-tiles x (2 mtiles x 4 ntiles x 3 split terms) mma ---- */
        uint2 Bb[2][4][2];
        {
            const __nv_bfloat16* gb = gBw;   /* kt = 0 */
#pragma unroll
            for (int nt = 0; nt < 4; nt++) {
                Bb[0][nt][0] = *(const uint2*)(gb + nt * 256);
                Bb[0][nt][1] = *(const uint2*)(gb + nt * 256 + 128);
            }
        }
#pragma unroll 2
        for (int kt = 0; kt < 16; kt++) {
            const int cur = kt & 1, nxt = cur ^ 1;
            if (kt < 15) {
                const __nv_bfloat16* gb = gBw + (size_t)(kt + 1) * 16384;
#pragma unroll
                for (int nt = 0; nt < 4; nt++) {
                    Bb[nxt][nt][0] = *(const uint2*)(gb + nt * 256);
                    Bb[nxt][nt][1] = *(const uint2*)(gb + nt * 256 + 128);
                }
            }
            const int kb = kt * 16 + 2 * cp;
#pragma unroll
            for (int mt = 0; mt < 2; mt++) {
                const int ra = (mt * 16 + r0) * APST;
                u32 Ah[4], Al[4];
                Ah[0] = *(const u32*)&Ahi[ra + kb];
                Ah[1] = *(const u32*)&Ahi[ra + 8 * APST + kb];
                Ah[2] = *(const u32*)&Ahi[ra + kb + 8];
                Ah[3] = *(const u32*)&Ahi[ra + 8 * APST + kb + 8];
                Al[0] = *(const u32*)&Alo[ra + kb];
                Al[1] = *(const u32*)&Alo[ra + 8 * APST + kb];
                Al[2] = *(const u32*)&Alo[ra + kb + 8];
                Al[3] = *(const u32*)&Alo[ra + 8 * APST + kb + 8];
#pragma unroll
                for (int nt = 0; nt < 4; nt++) {
                    mma16816(D[mt][nt], Ah, Bb[cur][nt][0].x, Bb[cur][nt][0].y); /* hi*Bhi */
                    mma16816(D[mt][nt], Ah, Bb[cur][nt][1].x, Bb[cur][nt][1].y); /* hi*Blo */
                    mma16816(D[mt][nt], Al, Bb[cur][nt][0].x, Bb[cur][nt][0].y); /* lo*Bhi */
                }
            }
        }
        __syncthreads();   /* S3: GEMM reads of A done */

        /* ---- LSTM pointwise (i,f,g,o of each (row,cell-pair) in this thread) ---- */
#pragma unroll
        for (int mt = 0; mt < 2; mt++) {
#pragma unroll
            for (int half = 0; half < 2; half++) {
                const int r = mt * 16 + r0 + 8 * half;
                float hh[2];
#pragma unroll
                for (int cc = 0; cc < 2; cc++) {
                    const int e = 2 * half + cc;
                    float iv = sigm(D[mt][0][e]);
                    float fv = sigm(D[mt][1][e]);
                    float gv = tanh_f(D[mt][2][e]);
                    float ov = sigm(D[mt][3][e]);
                    const int ci = mt * 4 + half * 2 + cc;
                    cst[ci] = fmaf(fv, cst[ci], iv * gv);
                    hh[cc] = ov * tanh_f(cst[ci]);
                    D[mt][0][e] = bia[0][cc]; D[mt][1][e] = bia[1][cc];
                    D[mt][2][e] = bia[2][cc]; D[mt][3][e] = bia[3][cc];
                }
                *(float2*)&Hs[r * HSST + cell0] = make_float2(hh[0], hh[1]);
                __nv_bfloat16 h0 = __float2bfloat16_rn(hh[0]);
                __nv_bfloat16 h1 = __float2bfloat16_rn(hh[1]);
                *(__nv_bfloat162*)&Ahi[r * APST + EMD + cell0] = __nv_bfloat162(h0, h1);
                *(__nv_bfloat162*)&Alo[r * APST + EMD + cell0] = __nv_bfloat162(
                    __float2bfloat16_rn(hh[0] - __bfloat162float(h0)),
                    __float2bfloat16_rn(hh[1] - __bfloat162float(h1)));
            }
        }
        __syncthreads();   /* S4: Hs ready */

        /* ---- output MLP: y[32,5] = h @ Wo^T + bo ---- */
        if (tid < ROWS * DOUT) {
            int r = tid / DOUT, d = tid % DOUT;
            float s = bo_r;
            const float* hrow = Hs + r * HSST;
            const float* wrow = WoS + d * WOST;
#pragma unroll 16
            for (int j = 0; j < CELL; j++) s = fmaf(hrow[j], wrow[j], s);
            out[((size_t)(row0 + r) * TSZ + t) * DOUT + d] = s;
        }
    }

    /* ---- tail: final h (Hs, coalesced) and c (registers) ---- */
    size_t baseH = (size_t)BSZ * TSZ * DOUT;
    size_t baseC = baseH + (size_t)BSZ * CELL;
#pragma unroll
    for (int i = 0; i < 8; i++) {
        int idx = tid + i * NTHR;
        int r = idx >> 7, c = idx & 127;
        out[baseH + (size_t)(row0 + r) * CELL + c] = Hs[r * HSST + c];
    }
#pragma unroll
    for (int mt = 0; mt < 2; mt++)
#pragma unroll
        for (int half = 0; half < 2; half++) {
            int r = mt * 16 + r0 + 8 * half;
            *(float2*)&out[baseC + (size_t)(row0 + r) * CELL + cell0] =
                make_float2(cst[mt * 4 + half * 2], cst[mt * 4 + half * 2 + 1]);
        }
}

/* ---------------- launch: 2 graph nodes ---------------- */
extern "C" void kernel_launch(void* const* d_in, const int* in_sizes, int n_in,
                              void* d_out, int out_size) {
    const float* inputs = (const float*)d_in[0];
    const float* We     = (const float*)d_in[1];
    const float* be     = (const float*)d_in[2];
    const float* W_ih   = (const float*)d_in[3];
    const float* W_hh   = (const float*)d_in[4];
    const float* b_ih   = (const float*)d_in[5];
    const float* b_hh   = (const float*)d_in[6];
    const float* Wo     = (const float*)d_in[7];
    const float* bo     = (const float*)d_in[8];
    float* out = (float*)d_out;

    static int smem_set = 0;
    if (!smem_set) {
        cudaFuncSetAttribute(lstm_persist, cudaFuncAttributeMaxDynamicSharedMemorySize,
                             SMEM_BYTES);
        smem_set = 1;
    }

    setup_kernel<<<(NBF + 255) / 256, 256>>>(W_ih, W_hh, b_ih, b_hh);
    lstm_persist<<<NCTA, NTHR, SMEM_BYTES>>>(inputs, We, be, Wo, bo, out);
}